// round 10
// baseline (speedup 1.0000x reference)
#include <cuda_runtime.h>
#include <cuda_bf16.h>
#include <cstdint>

#define N_MAX 100000
#define E_MAX 3200000
#define SCAN_BLOCKS 128
#define SCAN_THREADS 256

// -------------------- device scratch --------------------
__device__ float g_agg[(size_t)N_MAX * 256];
__device__ float g_h[(size_t)N_MAX * 256];
__device__ float g_tmp[(size_t)N_MAX * 256];
__device__ __nv_bfloat16 g_hbf[(size_t)N_MAX * 256];
__device__ int   g_count[N_MAX + 1];
__device__ int   g_rowptr[N_MAX + 1];
__device__ int   g_cursor[N_MAX];
__device__ float g_invdeg[N_MAX];
__device__ int   g_srcs[E_MAX];
__device__ int   g_is64;
__device__ int   g_bsum[SCAN_BLOCKS];
__device__ int   g_boff[SCAN_BLOCKS];

// -------------------- dtype detection --------------------
__global__ void detect_kernel(const void* ei, int Nn) {
    const long long* p = (const long long*)ei;
    int t = threadIdx.x;
    long long v = p[t];
    int bad = (v < 0 || v >= (long long)Nn);
    unsigned m = __ballot_sync(0xFFFFFFFFu, bad);
    __shared__ unsigned sm[2];
    if ((t & 31) == 0) sm[t >> 5] = m;
    __syncthreads();
    if (t == 0) g_is64 = (sm[0] | sm[1]) == 0u;
}

__device__ __forceinline__ int load_idx(const void* ei, long long pos) {
    if (g_is64) return (int)((const long long*)ei)[pos];
    return ((const int*)ei)[pos];
}

// -------------------- CSR build --------------------
__global__ void zero_count_kernel(int n) {
    int i = blockIdx.x * blockDim.x + threadIdx.x;
    if (i <= n) g_count[i] = 0;
}

__global__ void hist_kernel(const void* __restrict__ ei, int E) {
    int e = blockIdx.x * blockDim.x + threadIdx.x;
    if (e < E) atomicAdd(&g_count[load_idx(ei, (long long)E + e)], 1);
}

__device__ __forceinline__ void chunk_bounds(int Nn, int b, int t, int& tb, int& te) {
    int chunk = (Nn + SCAN_BLOCKS - 1) / SCAN_BLOCKS;
    int bbeg = b * chunk;
    int bend = min(bbeg + chunk, Nn);
    int tCH = (chunk + SCAN_THREADS - 1) / SCAN_THREADS;
    tb = bbeg + t * tCH;
    te = min(tb + tCH, bend);
}

__global__ void scan_p1(int Nn) {
    __shared__ int sh[SCAN_THREADS];
    int b = blockIdx.x, t = threadIdx.x;
    int tb, te; chunk_bounds(Nn, b, t, tb, te);
    int s = 0;
    for (int i = tb; i < te; i++) s += g_count[i];
    sh[t] = s;
    __syncthreads();
    for (int off = SCAN_THREADS / 2; off > 0; off >>= 1) {
        if (t < off) sh[t] += sh[t + off];
        __syncthreads();
    }
    if (t == 0) g_bsum[b] = sh[0];
}

__global__ void scan_p2(int Ee, int Nn) {
    __shared__ int sh[SCAN_BLOCKS];
    int t = threadIdx.x;
    int v = (t < SCAN_BLOCKS) ? g_bsum[t] : 0;
    if (t < SCAN_BLOCKS) sh[t] = v;
    __syncthreads();
    for (int off = 1; off < SCAN_BLOCKS; off <<= 1) {
        int u = 0;
        if (t < SCAN_BLOCKS && t >= off) u = sh[t - off];
        __syncthreads();
        if (t < SCAN_BLOCKS && t >= off) sh[t] += u;
        __syncthreads();
    }
    if (t < SCAN_BLOCKS) g_boff[t] = sh[t] - v;
    if (t == 0) g_rowptr[Nn] = Ee;
}

__global__ void scan_p3(int Nn) {
    __shared__ int sh[SCAN_THREADS];
    int b = blockIdx.x, t = threadIdx.x;
    int tb, te; chunk_bounds(Nn, b, t, tb, te);
    int s = 0;
    for (int i = tb; i < te; i++) s += g_count[i];
    sh[t] = s;
    __syncthreads();
    for (int off = 1; off < SCAN_THREADS; off <<= 1) {
        int u = 0;
        if (t >= off) u = sh[t - off];
        __syncthreads();
        if (t >= off) sh[t] += u;
        __syncthreads();
    }
    int run = sh[t] - s + g_boff[b];
    for (int i = tb; i < te; i++) {
        int c = g_count[i];
        g_rowptr[i] = run;
        g_cursor[i] = run;
        g_invdeg[i] = 1.0f / (float)max(c, 1);
        run += c;
    }
}

__global__ void scatter_kernel(const void* __restrict__ ei, int E) {
    int e = blockIdx.x * blockDim.x + threadIdx.x;
    if (e < E) {
        int s = load_idx(ei, e);
        int d = load_idx(ei, (long long)E + e);
        int pos = atomicAdd(&g_cursor[d], 1);
        g_srcs[pos] = s;
    }
}

// -------------------- mean aggregation (fp32 gather, 128 features) ----------
// processes dst nodes [n0, n1)
__global__ void agg_f32_kernel(const float4* __restrict__ X, float4* __restrict__ out,
                               int n0, int n1) {
    int w = n0 + ((blockIdx.x * blockDim.x + threadIdx.x) >> 5);
    int lane = threadIdx.x & 31;
    if (w >= n1) return;
    int beg = g_rowptr[w];
    int end = g_rowptr[w + 1];
    float4 acc = make_float4(0.f, 0.f, 0.f, 0.f);
    for (int e = beg; e < end; e++) {
        int s = g_srcs[e];
        float4 v = __ldg(&X[(size_t)s * 32 + lane]);
        acc.x += v.x; acc.y += v.y; acc.z += v.z; acc.w += v.w;
    }
    float inv = g_invdeg[w];
    float4 r;
    r.x = acc.x * inv; r.y = acc.y * inv; r.z = acc.z * inv; r.w = acc.w * inv;
    out[(size_t)w * 32 + lane] = r;
}

// -------------------- mean aggregation (bf16 gather, 256 features) ----------
__global__ void agg_bf16_kernel(const __nv_bfloat16* __restrict__ Xb,
                                float4* __restrict__ out, int n0, int n1) {
    int w = n0 + ((blockIdx.x * blockDim.x + threadIdx.x) >> 5);
    int lane = threadIdx.x & 31;
    if (w >= n1) return;
    int beg = g_rowptr[w];
    int end = g_rowptr[w + 1];
    float acc[8];
#pragma unroll
    for (int i = 0; i < 8; i++) acc[i] = 0.f;
    for (int e = beg; e < end; e++) {
        int s = g_srcs[e];
        const uint4* row = (const uint4*)(Xb + (size_t)s * 256);
        uint4 v = __ldg(&row[lane]);
        float2 f0 = __bfloat1622float2(*(__nv_bfloat162*)&v.x);
        float2 f1 = __bfloat1622float2(*(__nv_bfloat162*)&v.y);
        float2 f2 = __bfloat1622float2(*(__nv_bfloat162*)&v.z);
        float2 f3 = __bfloat1622float2(*(__nv_bfloat162*)&v.w);
        acc[0] += f0.x; acc[1] += f0.y;
        acc[2] += f1.x; acc[3] += f1.y;
        acc[4] += f2.x; acc[5] += f2.y;
        acc[6] += f3.x; acc[7] += f3.y;
    }
    float inv = g_invdeg[w];
    float4 r0, r1;
    r0.x = acc[0] * inv; r0.y = acc[1] * inv; r0.z = acc[2] * inv; r0.w = acc[3] * inv;
    r1.x = acc[4] * inv; r1.y = acc[5] * inv; r1.z = acc[6] * inv; r1.w = acc[7] * inv;
    out[(size_t)w * 64 + lane * 2]     = r0;
    out[(size_t)w * 64 + lane * 2 + 1] = r1;
}

// -------------------- TF32 tensor-core GEMM (mma.sync m16n8k8) --------------------
// C = act( A1@B1 [+ A2@B2] + bias? + Cin? ), optional bf16 mirror.
// Processes rows [row0, row0 + gridDim.y*128) clipped to M.

#define TBM 128
#define TBK 32
#define KSTR 36

__device__ __forceinline__ uint32_t f2tf32(float f) {
    uint32_t u;
    asm("cvt.rna.tf32.f32 %0, %1;" : "=r"(u) : "f"(f));
    return u;
}

__device__ __forceinline__ void mma_tf32(float c[4],
                                         uint32_t a0, uint32_t a1, uint32_t a2, uint32_t a3,
                                         uint32_t b0, uint32_t b1) {
    asm volatile(
        "mma.sync.aligned.m16n8k8.row.col.f32.tf32.tf32.f32 "
        "{%0,%1,%2,%3}, {%4,%5,%6,%7}, {%8,%9}, {%0,%1,%2,%3};"
        : "+f"(c[0]), "+f"(c[1]), "+f"(c[2]), "+f"(c[3])
        : "r"(a0), "r"(a1), "r"(a2), "r"(a3), "r"(b0), "r"(b1));
}

template <int NTILES>
__global__ __launch_bounds__(256) void gemm_tf32_kernel(
    const float* __restrict__ A1, int lda1, int K1,
    const float* __restrict__ A2, int lda2, int K2,   // A2 nullable (K2=0)
    const float* __restrict__ B1, const float* __restrict__ B2,
    const float* __restrict__ bias,                   // nullable
    const float* __restrict__ Cin,                    // nullable
    float* __restrict__ C, int ldc,
    __nv_bfloat16* __restrict__ Cbf,                  // nullable
    int row0, int M, int Ncol, int do_relu)
{
    constexpr int TBN = NTILES * 16;
    constexpr int B_IT = TBN / 32;
    constexpr int NQ4 = TBN / 4;

    __shared__ uint32_t As[TBM][KSTR];
    __shared__ uint32_t Bs[TBN][KSTR];

    int tid = threadIdx.x;
    int lane = tid & 31;
    int wid = tid >> 5;
    int grp = lane >> 2;
    int q = lane & 3;
    int warp_m = (wid & 3) * 32;
    int warp_n = (wid >> 2) * (NTILES * 8);
    int rowbase = row0 + blockIdx.y * TBM;
    int colbase = blockIdx.x * TBN;

    float acc[2][NTILES][4];
#pragma unroll
    for (int mt = 0; mt < 2; mt++)
#pragma unroll
        for (int nt = 0; nt < NTILES; nt++)
#pragma unroll
            for (int r = 0; r < 4; r++) acc[mt][nt][r] = 0.f;

    int K = K1 + K2;
    float4 ar[4], br[B_IT];

    // prologue: load tile 0 into regs
    {
        const float* Ap = A1; const float* Bp = B1; int lda = lda1, koff = 0;
#pragma unroll
        for (int it = 0; it < 4; it++) {
            int idx = tid + it * 256;
            int row = idx >> 3, kq = (idx & 7) * 4;
            int r = rowbase + row;
            ar[it] = make_float4(0.f, 0.f, 0.f, 0.f);
            if (r < M) ar[it] = *(const float4*)&Ap[(size_t)r * lda + koff + kq];
        }
#pragma unroll
        for (int it = 0; it < B_IT; it++) {
            int idx = tid + it * 256;
            int krow = idx / NQ4, nq = (idx % NQ4) * 4;
            br[it] = *(const float4*)&Bp[(size_t)(koff + krow) * Ncol + colbase + nq];
        }
    }

    for (int kbase = 0; kbase < K; kbase += TBK) {
        // regs -> smem (tf32 convert)
#pragma unroll
        for (int it = 0; it < 4; it++) {
            int idx = tid + it * 256;
            int row = idx >> 3, kq = (idx & 7) * 4;
            uint4 u;
            u.x = f2tf32(ar[it].x); u.y = f2tf32(ar[it].y);
            u.z = f2tf32(ar[it].z); u.w = f2tf32(ar[it].w);
            *(uint4*)&As[row][kq] = u;
        }
#pragma unroll
        for (int it = 0; it < B_IT; it++) {
            int idx = tid + it * 256;
            int krow = idx / NQ4, nq = (idx % NQ4) * 4;
            Bs[nq + 0][krow] = f2tf32(br[it].x);
            Bs[nq + 1][krow] = f2tf32(br[it].y);
            Bs[nq + 2][krow] = f2tf32(br[it].z);
            Bs[nq + 3][krow] = f2tf32(br[it].w);
        }
        __syncthreads();

        // prefetch next k-tile (overlaps MMA)
        int knext = kbase + TBK;
        if (knext < K) {
            const float* Ap; const float* Bp; int lda, koff;
            if (knext < K1) { Ap = A1; lda = lda1; Bp = B1; koff = knext; }
            else            { Ap = A2; lda = lda2; Bp = B2; koff = knext - K1; }
#pragma unroll
            for (int it = 0; it < 4; it++) {
                int idx = tid + it * 256;
                int row = idx >> 3, kq = (idx & 7) * 4;
                int r = rowbase + row;
                ar[it] = make_float4(0.f, 0.f, 0.f, 0.f);
                if (r < M) ar[it] = *(const float4*)&Ap[(size_t)r * lda + koff + kq];
            }
#pragma unroll
            for (int it = 0; it < B_IT; it++) {
                int idx = tid + it * 256;
                int krow = idx / NQ4, nq = (idx % NQ4) * 4;
                br[it] = *(const float4*)&Bp[(size_t)(koff + krow) * Ncol + colbase + nq];
            }
        }

        // MMA over smem tile
#pragma unroll
        for (int kc = 0; kc < TBK; kc += 8) {
            uint32_t a[2][4];
#pragma unroll
            for (int mt = 0; mt < 2; mt++) {
                int r = warp_m + mt * 16 + grp;
                a[mt][0] = As[r][kc + q];
                a[mt][1] = As[r + 8][kc + q];
                a[mt][2] = As[r][kc + q + 4];
                a[mt][3] = As[r + 8][kc + q + 4];
            }
#pragma unroll
            for (int nt = 0; nt < NTILES; nt++) {
                int c = warp_n + nt * 8 + grp;
                uint32_t b0 = Bs[c][kc + q];
                uint32_t b1 = Bs[c][kc + q + 4];
#pragma unroll
                for (int mt = 0; mt < 2; mt++)
                    mma_tf32(acc[mt][nt], a[mt][0], a[mt][1], a[mt][2], a[mt][3], b0, b1);
            }
        }
        __syncthreads();
    }

    // ---- epilogue ----
#pragma unroll
    for (int nt = 0; nt < NTILES; nt++) {
        int ccol = colbase + warp_n + nt * 8 + q * 2;
        float bv0 = 0.f, bv1 = 0.f;
        if (bias) { bv0 = bias[ccol]; bv1 = bias[ccol + 1]; }
#pragma unroll
        for (int mt = 0; mt < 2; mt++) {
            int r0 = rowbase + warp_m + mt * 16 + grp;
            int r1 = r0 + 8;
            float v0 = acc[mt][nt][0] + bv0;
            float v1 = acc[mt][nt][1] + bv1;
            float v2 = acc[mt][nt][2] + bv0;
            float v3 = acc[mt][nt][3] + bv1;
            if (Cin) {
                if (r0 < M) { float2 ci = *(const float2*)&Cin[(size_t)r0 * ldc + ccol]; v0 += ci.x; v1 += ci.y; }
                if (r1 < M) { float2 ci = *(const float2*)&Cin[(size_t)r1 * ldc + ccol]; v2 += ci.x; v3 += ci.y; }
            }
            if (do_relu) {
                v0 = fmaxf(v0, 0.f); v1 = fmaxf(v1, 0.f);
                v2 = fmaxf(v2, 0.f); v3 = fmaxf(v3, 0.f);
            }
            if (r0 < M) {
                float2 o = {v0, v1};
                *(float2*)&C[(size_t)r0 * ldc + ccol] = o;
                if (Cbf) *(__nv_bfloat162*)&Cbf[(size_t)r0 * ldc + ccol] = __floats2bfloat162_rn(v0, v1);
            }
            if (r1 < M) {
                float2 o = {v2, v3};
                *(float2*)&C[(size_t)r1 * ldc + ccol] = o;
                if (Cbf) *(__nv_bfloat162*)&Cbf[(size_t)r1 * ldc + ccol] = __floats2bfloat162_rn(v2, v3);
            }
        }
    }
}

// -------------------- launch --------------------
extern "C" void kernel_launch(void* const* d_in, const int* in_sizes, int n_in,
                              void* d_out, int out_size) {
    const float* x   = (const float*)d_in[0];
    const void*  ei  = d_in[1];
    const float* Wl0 = (const float*)d_in[2];
    const float* Wr0 = (const float*)d_in[3];
    const float* b0  = (const float*)d_in[4];
    const float* Wl1 = (const float*)d_in[5];
    const float* Wr1 = (const float*)d_in[6];
    const float* b1  = (const float*)d_in[7];
    const float* Wf  = (const float*)d_in[8];
    const float* bf  = (const float*)d_in[9];
    (void)n_in; (void)out_size;

    int Nn = in_sizes[0] / 128;   // 100000
    int Ee = in_sizes[1] / 2;     // 3200000

    float* out = (float*)d_out;                 // [N, 64]
    float* emb = out + (size_t)Nn * 64;         // [N, 256]

    void *p_agg, *p_h, *p_tmp, *p_hbf;
    cudaGetSymbolAddress(&p_agg, g_agg);
    cudaGetSymbolAddress(&p_h, g_h);
    cudaGetSymbolAddress(&p_tmp, g_tmp);
    cudaGetSymbolAddress(&p_hbf, g_hbf);
    float* agg = (float*)p_agg;
    float* h   = (float*)p_h;
    float* tmp = (float*)p_tmp;
    __nv_bfloat16* hbf = (__nv_bfloat16*)p_hbf;

    // row halves, tile-aligned
    int tiles  = (Nn + TBM - 1) / TBM;          // 782
    int t0     = (tiles + 1) / 2;               // 391
    int Mh     = t0 * TBM;                      // 50048
    int t1     = tiles - t0;                    // 391
    dim3 grid_h0(2, t0), grid_h1(2, t1);
    dim3 grid_full(2, tiles);
    dim3 grid_head(1, tiles);

    int aggblk0 = (Mh + 7) / 8;                 // warps-per-block = 8
    int aggblk1 = (Nn - Mh + 7) / 8;

    // side stream + events (host objects; leaked, few calls ever, replays use graph)
    cudaStream_t s2;
    cudaStreamCreateWithFlags(&s2, cudaStreamNonBlocking);
    cudaEvent_t evFork, evA0h0, evA0h1, evJ0done, evA1h0, evA1h1, evEnd;
    cudaEventCreateWithFlags(&evFork,  cudaEventDisableTiming);
    cudaEventCreateWithFlags(&evA0h0,  cudaEventDisableTiming);
    cudaEventCreateWithFlags(&evA0h1,  cudaEventDisableTiming);
    cudaEventCreateWithFlags(&evJ0done,cudaEventDisableTiming);
    cudaEventCreateWithFlags(&evA1h0,  cudaEventDisableTiming);
    cudaEventCreateWithFlags(&evA1h1,  cudaEventDisableTiming);
    cudaEventCreateWithFlags(&evEnd,   cudaEventDisableTiming);

    // 0) dtype detect (main)
    detect_kernel<<<1, 64>>>(ei, Nn);

    // fork s2
    cudaEventRecord(evFork, 0);
    cudaStreamWaitEvent(s2, evFork, 0);

    // s2: side GEMM tmp = x@Wl0 + b0 (full rows)
    gemm_tf32_kernel<8><<<grid_full, 256, 0, s2>>>(
        x, 128, 128, nullptr, 0, 0, Wl0, nullptr, b0, nullptr,
        tmp, 256, nullptr, 0, Nn, 256, 0);

    // main: CSR build
    zero_count_kernel<<<(Nn + 256) / 256, 256>>>(Nn);
    hist_kernel<<<(Ee + 255) / 256, 256>>>(ei, Ee);
    scan_p1<<<SCAN_BLOCKS, SCAN_THREADS>>>(Nn);
    scan_p2<<<1, SCAN_BLOCKS>>>(Ee, Nn);
    scan_p3<<<SCAN_BLOCKS, SCAN_THREADS>>>(Nn);
    scatter_kernel<<<(Ee + 255) / 256, 256>>>(ei, Ee);

    // main: agg0 halves
    agg_f32_kernel<<<aggblk0, 256>>>((const float4*)x, (float4*)agg, 0, Mh);
    cudaEventRecord(evA0h0, 0);
    agg_f32_kernel<<<aggblk1, 256>>>((const float4*)x, (float4*)agg, Mh, Nn);
    cudaEventRecord(evA0h1, 0);

    // s2: join0 halves  h = relu(tmp + agg@Wr0), emit hbf
    cudaStreamWaitEvent(s2, evA0h0, 0);
    gemm_tf32_kernel<8><<<grid_h0, 256, 0, s2>>>(
        agg, 128, 128, nullptr, 0, 0, Wr0, nullptr, nullptr, tmp,
        h, 256, hbf, 0, Nn, 256, 1);
    cudaStreamWaitEvent(s2, evA0h1, 0);
    gemm_tf32_kernel<8><<<grid_h1, 256, 0, s2>>>(
        agg, 128, 128, nullptr, 0, 0, Wr0, nullptr, nullptr, tmp,
        h, 256, hbf, Mh, Nn, 256, 1);
    cudaEventRecord(evJ0done, s2);

    // main: agg1 halves (needs full hbf)
    cudaStreamWaitEvent(0, evJ0done, 0);
    agg_bf16_kernel<<<aggblk0, 256>>>(hbf, (float4*)agg, 0, Mh);
    cudaEventRecord(evA1h0, 0);
    agg_bf16_kernel<<<aggblk1, 256>>>(hbf, (float4*)agg, Mh, Nn);
    cudaEventRecord(evA1h1, 0);

    // s2: fused gemm1 halves  emb = relu([h|agg]@[Wl1;Wr1] + b1)
    cudaStreamWaitEvent(s2, evA1h0, 0);
    gemm_tf32_kernel<8><<<grid_h0, 256, 0, s2>>>(
        h, 256, 256, agg, 256, 256, Wl1, Wr1, b1, nullptr,
        emb, 256, nullptr, 0, Nn, 256, 1);
    cudaStreamWaitEvent(s2, evA1h1, 0);
    gemm_tf32_kernel<8><<<grid_h1, 256, 0, s2>>>(
        h, 256, 256, agg, 256, 256, Wl1, Wr1, b1, nullptr,
        emb, 256, nullptr, Mh, Nn, 256, 1);

    // s2: head  out = emb @ Wf + bf (full rows; in-order after gemm1 halves)
    gemm_tf32_kernel<4><<<grid_head, 256, 0, s2>>>(
        emb, 256, 256, nullptr, 0, 0, Wf, nullptr, bf, nullptr,
        out, 64, nullptr, 0, Nn, 64, 0);

    // join back to main
    cudaEventRecord(evEnd, s2);
    cudaStreamWaitEvent(0, evEnd, 0);
}

// round 12
// speedup vs baseline: 1.1303x; 1.1303x over previous
#include <cuda_runtime.h>
#include <cuda_bf16.h>
#include <cstdint>

#define N_MAX 100000
#define E_MAX 3200000
#define SCAN_BLOCKS 128
#define SCAN_THREADS 256

// -------------------- device scratch --------------------
__device__ float g_agg[(size_t)N_MAX * 256];
__device__ float g_h[(size_t)N_MAX * 256];
__device__ __nv_bfloat16 g_hbf[(size_t)N_MAX * 256];
__device__ int   g_count[N_MAX + 1];
__device__ int   g_rowptr[N_MAX + 1];
__device__ int   g_cursor[N_MAX];
__device__ float g_invdeg[N_MAX];
__device__ int   g_srcs[E_MAX];
__device__ int   g_is64;
__device__ int   g_bsum[SCAN_BLOCKS];
__device__ int   g_boff[SCAN_BLOCKS];

// -------------------- dtype detection --------------------
__global__ void detect_kernel(const void* ei, int Nn) {
    const long long* p = (const long long*)ei;
    int t = threadIdx.x;
    long long v = p[t];
    int bad = (v < 0 || v >= (long long)Nn);
    unsigned m = __ballot_sync(0xFFFFFFFFu, bad);
    __shared__ unsigned sm[2];
    if ((t & 31) == 0) sm[t >> 5] = m;
    __syncthreads();
    if (t == 0) g_is64 = (sm[0] | sm[1]) == 0u;
}

__device__ __forceinline__ int load_idx(const void* ei, long long pos) {
    if (g_is64) return (int)((const long long*)ei)[pos];
    return ((const int*)ei)[pos];
}

// -------------------- CSR build --------------------
__global__ void zero_count_kernel(int n) {
    int i = blockIdx.x * blockDim.x + threadIdx.x;
    if (i <= n) g_count[i] = 0;
}

__global__ void hist_kernel(const void* __restrict__ ei, int E) {
    int e = blockIdx.x * blockDim.x + threadIdx.x;
    if (e < E) atomicAdd(&g_count[load_idx(ei, (long long)E + e)], 1);
}

__device__ __forceinline__ void chunk_bounds(int Nn, int b, int t, int& tb, int& te) {
    int chunk = (Nn + SCAN_BLOCKS - 1) / SCAN_BLOCKS;
    int bbeg = b * chunk;
    int bend = min(bbeg + chunk, Nn);
    int tCH = (chunk + SCAN_THREADS - 1) / SCAN_THREADS;
    tb = bbeg + t * tCH;
    te = min(tb + tCH, bend);
}

__global__ void scan_p1(int Nn) {
    __shared__ int sh[SCAN_THREADS];
    int b = blockIdx.x, t = threadIdx.x;
    int tb, te; chunk_bounds(Nn, b, t, tb, te);
    int s = 0;
    for (int i = tb; i < te; i++) s += g_count[i];
    sh[t] = s;
    __syncthreads();
    for (int off = SCAN_THREADS / 2; off > 0; off >>= 1) {
        if (t < off) sh[t] += sh[t + off];
        __syncthreads();
    }
    if (t == 0) g_bsum[b] = sh[0];
}

__global__ void scan_p2(int Ee, int Nn) {
    __shared__ int sh[SCAN_BLOCKS];
    int t = threadIdx.x;
    int v = (t < SCAN_BLOCKS) ? g_bsum[t] : 0;
    if (t < SCAN_BLOCKS) sh[t] = v;
    __syncthreads();
    for (int off = 1; off < SCAN_BLOCKS; off <<= 1) {
        int u = 0;
        if (t < SCAN_BLOCKS && t >= off) u = sh[t - off];
        __syncthreads();
        if (t < SCAN_BLOCKS && t >= off) sh[t] += u;
        __syncthreads();
    }
    if (t < SCAN_BLOCKS) g_boff[t] = sh[t] - v;
    if (t == 0) g_rowptr[Nn] = Ee;
}

__global__ void scan_p3(int Nn) {
    __shared__ int sh[SCAN_THREADS];
    int b = blockIdx.x, t = threadIdx.x;
    int tb, te; chunk_bounds(Nn, b, t, tb, te);
    int s = 0;
    for (int i = tb; i < te; i++) s += g_count[i];
    sh[t] = s;
    __syncthreads();
    for (int off = 1; off < SCAN_THREADS; off <<= 1) {
        int u = 0;
        if (t >= off) u = sh[t - off];
        __syncthreads();
        if (t >= off) sh[t] += u;
        __syncthreads();
    }
    int run = sh[t] - s + g_boff[b];
    for (int i = tb; i < te; i++) {
        int c = g_count[i];
        g_rowptr[i] = run;
        g_cursor[i] = run;
        g_invdeg[i] = 1.0f / (float)max(c, 1);
        run += c;
    }
}

__global__ void scatter_kernel(const void* __restrict__ ei, int E) {
    int e = blockIdx.x * blockDim.x + threadIdx.x;
    if (e < E) {
        int s = load_idx(ei, e);
        int d = load_idx(ei, (long long)E + e);
        int pos = atomicAdd(&g_cursor[d], 1);
        g_srcs[pos] = s;
    }
}

// -------------------- mean aggregation (fp32 gather, 128 features) ----------
__global__ void agg_f32_kernel(const float4* __restrict__ X, float4* __restrict__ out, int Nn) {
    int w = (blockIdx.x * blockDim.x + threadIdx.x) >> 5;
    int lane = threadIdx.x & 31;
    if (w >= Nn) return;
    int beg = g_rowptr[w];
    int end = g_rowptr[w + 1];
    float4 acc = make_float4(0.f, 0.f, 0.f, 0.f);
    for (int e = beg; e < end; e++) {
        int s = g_srcs[e];
        float4 v = __ldg(&X[(size_t)s * 32 + lane]);
        acc.x += v.x; acc.y += v.y; acc.z += v.z; acc.w += v.w;
    }
    float inv = g_invdeg[w];
    float4 r;
    r.x = acc.x * inv; r.y = acc.y * inv; r.z = acc.z * inv; r.w = acc.w * inv;
    out[(size_t)w * 32 + lane] = r;
}

// -------------------- mean aggregation (bf16 gather, 256 features) ----------
__global__ void agg_bf16_kernel(const __nv_bfloat16* __restrict__ Xb,
                                float4* __restrict__ out, int Nn) {
    int w = (blockIdx.x * blockDim.x + threadIdx.x) >> 5;
    int lane = threadIdx.x & 31;
    if (w >= Nn) return;
    int beg = g_rowptr[w];
    int end = g_rowptr[w + 1];
    float acc[8];
#pragma unroll
    for (int i = 0; i < 8; i++) acc[i] = 0.f;
    for (int e = beg; e < end; e++) {
        int s = g_srcs[e];
        const uint4* row = (const uint4*)(Xb + (size_t)s * 256);
        uint4 v = __ldg(&row[lane]);
        float2 f0 = __bfloat1622float2(*(__nv_bfloat162*)&v.x);
        float2 f1 = __bfloat1622float2(*(__nv_bfloat162*)&v.y);
        float2 f2 = __bfloat1622float2(*(__nv_bfloat162*)&v.z);
        float2 f3 = __bfloat1622float2(*(__nv_bfloat162*)&v.w);
        acc[0] += f0.x; acc[1] += f0.y;
        acc[2] += f1.x; acc[3] += f1.y;
        acc[4] += f2.x; acc[5] += f2.y;
        acc[6] += f3.x; acc[7] += f3.y;
    }
    float inv = g_invdeg[w];
    float4 r0, r1;
    r0.x = acc[0] * inv; r0.y = acc[1] * inv; r0.z = acc[2] * inv; r0.w = acc[3] * inv;
    r1.x = acc[4] * inv; r1.y = acc[5] * inv; r1.z = acc[6] * inv; r1.w = acc[7] * inv;
    out[(size_t)w * 64 + lane * 2]     = r0;
    out[(size_t)w * 64 + lane * 2 + 1] = r1;
}

// -------------------- TF32 tensor-core GEMM (mma.sync m16n8k8) --------------------
// C = act( A1@B1 [+ A2@B2] + bias? ), optional bf16 mirror of C.
// Block tile 128 x (NTILES*16) x 32, 8 warps, pipelined gmem->reg prefetch.

#define TBM 128
#define TBK 32
#define KSTR 36

__device__ __forceinline__ uint32_t f2tf32(float f) {
    uint32_t u;
    asm("cvt.rna.tf32.f32 %0, %1;" : "=r"(u) : "f"(f));
    return u;
}

__device__ __forceinline__ void mma_tf32(float c[4],
                                         uint32_t a0, uint32_t a1, uint32_t a2, uint32_t a3,
                                         uint32_t b0, uint32_t b1) {
    asm volatile(
        "mma.sync.aligned.m16n8k8.row.col.f32.tf32.tf32.f32 "
        "{%0,%1,%2,%3}, {%4,%5,%6,%7}, {%8,%9}, {%0,%1,%2,%3};"
        : "+f"(c[0]), "+f"(c[1]), "+f"(c[2]), "+f"(c[3])
        : "r"(a0), "r"(a1), "r"(a2), "r"(a3), "r"(b0), "r"(b1));
}

template <int NTILES>
__global__ __launch_bounds__(256) void gemm_tf32_kernel(
    const float* __restrict__ A1, int lda1, int K1,
    const float* __restrict__ A2, int lda2, int K2,   // A2 nullable (K2=0)
    const float* __restrict__ B1, const float* __restrict__ B2,
    const float* __restrict__ bias,                   // nullable
    float* __restrict__ C, int ldc,
    __nv_bfloat16* __restrict__ Cbf,                  // nullable
    int M, int Ncol, int do_relu)
{
    constexpr int TBN = NTILES * 16;
    constexpr int B_IT = TBN / 32;
    constexpr int NQ4 = TBN / 4;

    __shared__ uint32_t As[TBM][KSTR];
    __shared__ uint32_t Bs[TBN][KSTR];

    int tid = threadIdx.x;
    int lane = tid & 31;
    int wid = tid >> 5;
    int grp = lane >> 2;
    int q = lane & 3;
    int warp_m = (wid & 3) * 32;
    int warp_n = (wid >> 2) * (NTILES * 8);
    int rowbase = blockIdx.y * TBM;
    int colbase = blockIdx.x * TBN;

    float acc[2][NTILES][4];
#pragma unroll
    for (int mt = 0; mt < 2; mt++)
#pragma unroll
        for (int nt = 0; nt < NTILES; nt++)
#pragma unroll
            for (int r = 0; r < 4; r++) acc[mt][nt][r] = 0.f;

    int K = K1 + K2;
    float4 ar[4], br[B_IT];

    // prologue: load tile 0 into regs
    {
        const float* Ap = A1; const float* Bp = B1; int lda = lda1, koff = 0;
#pragma unroll
        for (int it = 0; it < 4; it++) {
            int idx = tid + it * 256;
            int row = idx >> 3, kq = (idx & 7) * 4;
            int r = rowbase + row;
            ar[it] = make_float4(0.f, 0.f, 0.f, 0.f);
            if (r < M) ar[it] = *(const float4*)&Ap[(size_t)r * lda + koff + kq];
        }
#pragma unroll
        for (int it = 0; it < B_IT; it++) {
            int idx = tid + it * 256;
            int krow = idx / NQ4, nq = (idx % NQ4) * 4;
            br[it] = *(const float4*)&Bp[(size_t)(koff + krow) * Ncol + colbase + nq];
        }
    }

    for (int kbase = 0; kbase < K; kbase += TBK) {
        // regs -> smem (tf32 convert)
#pragma unroll
        for (int it = 0; it < 4; it++) {
            int idx = tid + it * 256;
            int row = idx >> 3, kq = (idx & 7) * 4;
            uint4 u;
            u.x = f2tf32(ar[it].x); u.y = f2tf32(ar[it].y);
            u.z = f2tf32(ar[it].z); u.w = f2tf32(ar[it].w);
            *(uint4*)&As[row][kq] = u;
        }
#pragma unroll
        for (int it = 0; it < B_IT; it++) {
            int idx = tid + it * 256;
            int krow = idx / NQ4, nq = (idx % NQ4) * 4;
            Bs[nq + 0][krow] = f2tf32(br[it].x);
            Bs[nq + 1][krow] = f2tf32(br[it].y);
            Bs[nq + 2][krow] = f2tf32(br[it].z);
            Bs[nq + 3][krow] = f2tf32(br[it].w);
        }
        __syncthreads();

        // prefetch next k-tile (overlaps MMA)
        int knext = kbase + TBK;
        if (knext < K) {
            const float* Ap; const float* Bp; int lda, koff;
            if (knext < K1) { Ap = A1; lda = lda1; Bp = B1; koff = knext; }
            else            { Ap = A2; lda = lda2; Bp = B2; koff = knext - K1; }
#pragma unroll
            for (int it = 0; it < 4; it++) {
                int idx = tid + it * 256;
                int row = idx >> 3, kq = (idx & 7) * 4;
                int r = rowbase + row;
                ar[it] = make_float4(0.f, 0.f, 0.f, 0.f);
                if (r < M) ar[it] = *(const float4*)&Ap[(size_t)r * lda + koff + kq];
            }
#pragma unroll
            for (int it = 0; it < B_IT; it++) {
                int idx = tid + it * 256;
                int krow = idx / NQ4, nq = (idx % NQ4) * 4;
                br[it] = *(const float4*)&Bp[(size_t)(koff + krow) * Ncol + colbase + nq];
            }
        }

        // MMA over smem tile
#pragma unroll
        for (int kc = 0; kc < TBK; kc += 8) {
            uint32_t a[2][4];
#pragma unroll
            for (int mt = 0; mt < 2; mt++) {
                int r = warp_m + mt * 16 + grp;
                a[mt][0] = As[r][kc + q];
                a[mt][1] = As[r + 8][kc + q];
                a[mt][2] = As[r][kc + q + 4];
                a[mt][3] = As[r + 8][kc + q + 4];
            }
#pragma unroll
            for (int nt = 0; nt < NTILES; nt++) {
                int c = warp_n + nt * 8 + grp;
                uint32_t b0 = Bs[c][kc + q];
                uint32_t b1 = Bs[c][kc + q + 4];
#pragma unroll
                for (int mt = 0; mt < 2; mt++)
                    mma_tf32(acc[mt][nt], a[mt][0], a[mt][1], a[mt][2], a[mt][3], b0, b1);
            }
        }
        __syncthreads();
    }

    // ---- epilogue ----
#pragma unroll
    for (int nt = 0; nt < NTILES; nt++) {
        int ccol = colbase + warp_n + nt * 8 + q * 2;
        float bv0 = 0.f, bv1 = 0.f;
        if (bias) { bv0 = bias[ccol]; bv1 = bias[ccol + 1]; }
#pragma unroll
        for (int mt = 0; mt < 2; mt++) {
            int r0 = rowbase + warp_m + mt * 16 + grp;
            int r1 = r0 + 8;
            float v0 = acc[mt][nt][0] + bv0;
            float v1 = acc[mt][nt][1] + bv1;
            float v2 = acc[mt][nt][2] + bv0;
            float v3 = acc[mt][nt][3] + bv1;
            if (do_relu) {
                v0 = fmaxf(v0, 0.f); v1 = fmaxf(v1, 0.f);
                v2 = fmaxf(v2, 0.f); v3 = fmaxf(v3, 0.f);
            }
            if (r0 < M) {
                float2 o = {v0, v1};
                *(float2*)&C[(size_t)r0 * ldc + ccol] = o;
                if (Cbf) *(__nv_bfloat162*)&Cbf[(size_t)r0 * ldc + ccol] = __floats2bfloat162_rn(v0, v1);
            }
            if (r1 < M) {
                float2 o = {v2, v3};
                *(float2*)&C[(size_t)r1 * ldc + ccol] = o;
                if (Cbf) *(__nv_bfloat162*)&Cbf[(size_t)r1 * ldc + ccol] = __floats2bfloat162_rn(v2, v3);
            }
        }
    }
}

// -------------------- launch --------------------
extern "C" void kernel_launch(void* const* d_in, const int* in_sizes, int n_in,
                              void* d_out, int out_size) {
    const float* x   = (const float*)d_in[0];
    const void*  ei  = d_in[1];
    const float* Wl0 = (const float*)d_in[2];
    const float* Wr0 = (const float*)d_in[3];
    const float* b0  = (const float*)d_in[4];
    const float* Wl1 = (const float*)d_in[5];
    const float* Wr1 = (const float*)d_in[6];
    const float* b1  = (const float*)d_in[7];
    const float* Wf  = (const float*)d_in[8];
    const float* bf  = (const float*)d_in[9];
    (void)n_in; (void)out_size;

    int Nn = in_sizes[0] / 128;   // 100000
    int Ee = in_sizes[1] / 2;     // 3200000

    float* out = (float*)d_out;                 // [N, 64]
    float* emb = out + (size_t)Nn * 64;         // [N, 256]

    void *p_agg, *p_h, *p_hbf;
    cudaGetSymbolAddress(&p_agg, g_agg);
    cudaGetSymbolAddress(&p_h, g_h);
    cudaGetSymbolAddress(&p_hbf, g_hbf);
    float* agg = (float*)p_agg;
    float* h   = (float*)p_h;
    __nv_bfloat16* hbf = (__nv_bfloat16*)p_hbf;

    int tiles = (Nn + TBM - 1) / TBM;
    dim3 gemm_grid(2, tiles);       // TBN=128, Ncol=256
    dim3 head_grid(1, tiles);       // TBN=64,  Ncol=64

    // 0) dtype detect
    detect_kernel<<<1, 64>>>(ei, Nn);

    // 1) CSR build (by dst)
    zero_count_kernel<<<(Nn + 256) / 256, 256>>>(Nn);
    hist_kernel<<<(Ee + 255) / 256, 256>>>(ei, Ee);
    scan_p1<<<SCAN_BLOCKS, SCAN_THREADS>>>(Nn);
    scan_p2<<<1, SCAN_BLOCKS>>>(Ee, Nn);
    scan_p3<<<SCAN_BLOCKS, SCAN_THREADS>>>(Nn);
    scatter_kernel<<<(Ee + 255) / 256, 256>>>(ei, Ee);

    // 2) layer 0: agg0 then fused GEMM  h = relu([x|agg0]@[Wl0;Wr0] + b0), emit hbf
    agg_f32_kernel<<<(Nn + 7) / 8, 256>>>((const float4*)x, (float4*)agg, Nn);
    gemm_tf32_kernel<8><<<gemm_grid, 256>>>(
        x, 128, 128, agg, 128, 128, Wl0, Wr0, b0,
        h, 256, hbf, Nn, 256, 1);

    // 3) layer 1: bf16 agg1 then fused GEMM  emb = relu([h|agg1]@[Wl1;Wr1] + b1)
    agg_bf16_kernel<<<(Nn + 7) / 8, 256>>>(hbf, (float4*)agg, Nn);
    gemm_tf32_kernel<8><<<gemm_grid, 256>>>(
        h, 256, 256, agg, 256, 256, Wl1, Wr1, b1,
        emb, 256, nullptr, Nn, 256, 1);

    // 4) head: out = emb @ Wf + bf
    gemm_tf32_kernel<4><<<head_grid, 256>>>(
        emb, 256, 256, nullptr, 0, 0, Wf, nullptr, bf,
        out, 64, nullptr, Nn, 64, 0);
}

// round 14
// speedup vs baseline: 2.0472x; 1.8111x over previous
#include <cuda_runtime.h>
#include <cuda_fp16.h>
#include <cstdint>

#define N_MAX 100000
#define E_MAX 3200000
#define SCAN_BLOCKS 128
#define SCAN_THREADS 256

// -------------------- device scratch --------------------
__device__ float  g_agg[(size_t)N_MAX * 128];          // agg0 (fp32, 128 feats)
__device__ __half g_hf[(size_t)N_MAX * 256];           // h in f16
__device__ __half g_aggh[(size_t)N_MAX * 256];         // agg1 in f16
__device__ __half g_wt[256 * 256 + 256 * 512 + 64 * 256]; // W0t, W1t, Wft (K-major per out-col)
__device__ int   g_count[N_MAX + 1];
__device__ int   g_rowptr[N_MAX + 1];
__device__ int   g_cursor[N_MAX];
__device__ float g_invdeg[N_MAX];
__device__ int   g_srcs[E_MAX];
__device__ int   g_is64;
__device__ int   g_bsum[SCAN_BLOCKS];
__device__ int   g_boff[SCAN_BLOCKS];

// -------------------- dtype detection --------------------
__global__ void detect_kernel(const void* ei, int Nn) {
    const long long* p = (const long long*)ei;
    int t = threadIdx.x;
    long long v = p[t];
    int bad = (v < 0 || v >= (long long)Nn);
    unsigned m = __ballot_sync(0xFFFFFFFFu, bad);
    __shared__ unsigned sm[2];
    if ((t & 31) == 0) sm[t >> 5] = m;
    __syncthreads();
    if (t == 0) g_is64 = (sm[0] | sm[1]) == 0u;
}

__device__ __forceinline__ int load_idx(const void* ei, long long pos) {
    if (g_is64) return (int)((const long long*)ei)[pos];
    return ((const int*)ei)[pos];
}

// -------------------- CSR build --------------------
__global__ void zero_count_kernel(int n) {
    int i = blockIdx.x * blockDim.x + threadIdx.x;
    if (i <= n) g_count[i] = 0;
}

__global__ void hist_kernel(const void* __restrict__ ei, int E) {
    int e = blockIdx.x * blockDim.x + threadIdx.x;
    if (e < E) atomicAdd(&g_count[load_idx(ei, (long long)E + e)], 1);
}

__device__ __forceinline__ void chunk_bounds(int Nn, int b, int t, int& tb, int& te) {
    int chunk = (Nn + SCAN_BLOCKS - 1) / SCAN_BLOCKS;
    int bbeg = b * chunk;
    int bend = min(bbeg + chunk, Nn);
    int tCH = (chunk + SCAN_THREADS - 1) / SCAN_THREADS;
    tb = bbeg + t * tCH;
    te = min(tb + tCH, bend);
}

__global__ void scan_p1(int Nn) {
    __shared__ int sh[SCAN_THREADS];
    int b = blockIdx.x, t = threadIdx.x;
    int tb, te; chunk_bounds(Nn, b, t, tb, te);
    int s = 0;
    for (int i = tb; i < te; i++) s += g_count[i];
    sh[t] = s;
    __syncthreads();
    for (int off = SCAN_THREADS / 2; off > 0; off >>= 1) {
        if (t < off) sh[t] += sh[t + off];
        __syncthreads();
    }
    if (t == 0) g_bsum[b] = sh[0];
}

__global__ void scan_p2(int Ee, int Nn) {
    __shared__ int sh[SCAN_BLOCKS];
    int t = threadIdx.x;
    int v = (t < SCAN_BLOCKS) ? g_bsum[t] : 0;
    if (t < SCAN_BLOCKS) sh[t] = v;
    __syncthreads();
    for (int off = 1; off < SCAN_BLOCKS; off <<= 1) {
        int u = 0;
        if (t < SCAN_BLOCKS && t >= off) u = sh[t - off];
        __syncthreads();
        if (t < SCAN_BLOCKS && t >= off) sh[t] += u;
        __syncthreads();
    }
    if (t < SCAN_BLOCKS) g_boff[t] = sh[t] - v;
    if (t == 0) g_rowptr[Nn] = Ee;
}

__global__ void scan_p3(int Nn) {
    __shared__ int sh[SCAN_THREADS];
    int b = blockIdx.x, t = threadIdx.x;
    int tb, te; chunk_bounds(Nn, b, t, tb, te);
    int s = 0;
    for (int i = tb; i < te; i++) s += g_count[i];
    sh[t] = s;
    __syncthreads();
    for (int off = 1; off < SCAN_THREADS; off <<= 1) {
        int u = 0;
        if (t >= off) u = sh[t - off];
        __syncthreads();
        if (t >= off) sh[t] += u;
        __syncthreads();
    }
    int run = sh[t] - s + g_boff[b];
    for (int i = tb; i < te; i++) {
        int c = g_count[i];
        g_rowptr[i] = run;
        g_cursor[i] = run;
        g_invdeg[i] = 1.0f / (float)max(c, 1);
        run += c;
    }
}

__global__ void scatter_kernel(const void* __restrict__ ei, int E) {
    int e = blockIdx.x * blockDim.x + threadIdx.x;
    if (e < E) {
        int s = load_idx(ei, e);
        int d = load_idx(ei, (long long)E + e);
        int pos = atomicAdd(&g_cursor[d], 1);
        g_srcs[pos] = s;
    }
}

// -------------------- weight convert+transpose: Wt[n][Ktot] <- W[k][n] ----------
__global__ void wconv_kernel(const float* __restrict__ W, __half* __restrict__ Wt,
                             int koff, int Ksub, int Ktot, int N) {
    int idx = blockIdx.x * blockDim.x + threadIdx.x;
    if (idx >= Ksub * N) return;
    int k = idx / N, n = idx - k * N;
    Wt[(size_t)n * Ktot + koff + k] = __float2half_rn(W[(size_t)k * N + n]);
}

// -------------------- mean aggregation (fp32 gather, 128 features) ----------
__global__ void agg_f32_kernel(const float4* __restrict__ X, float4* __restrict__ out, int Nn) {
    int w = (blockIdx.x * blockDim.x + threadIdx.x) >> 5;
    int lane = threadIdx.x & 31;
    if (w >= Nn) return;
    int beg = g_rowptr[w];
    int end = g_rowptr[w + 1];
    float4 acc = make_float4(0.f, 0.f, 0.f, 0.f);
    for (int e = beg; e < end; e++) {
        int s = g_srcs[e];
        float4 v = __ldg(&X[(size_t)s * 32 + lane]);
        acc.x += v.x; acc.y += v.y; acc.z += v.z; acc.w += v.w;
    }
    float inv = g_invdeg[w];
    float4 r;
    r.x = acc.x * inv; r.y = acc.y * inv; r.z = acc.z * inv; r.w = acc.w * inv;
    out[(size_t)w * 32 + lane] = r;
}

// -------------------- mean aggregation (f16 gather, 256 features -> f16 out) ----
__global__ void agg_f16_kernel(const __half* __restrict__ Xh, __half* __restrict__ outh, int Nn) {
    int w = (blockIdx.x * blockDim.x + threadIdx.x) >> 5;
    int lane = threadIdx.x & 31;
    if (w >= Nn) return;
    int beg = g_rowptr[w];
    int end = g_rowptr[w + 1];
    float acc[8];
#pragma unroll
    for (int i = 0; i < 8; i++) acc[i] = 0.f;
    for (int e = beg; e < end; e++) {
        int s = g_srcs[e];
        const uint4* row = (const uint4*)(Xh + (size_t)s * 256);
        uint4 v = __ldg(&row[lane]);
        float2 f0 = __half22float2(*(__half2*)&v.x);
        float2 f1 = __half22float2(*(__half2*)&v.y);
        float2 f2 = __half22float2(*(__half2*)&v.z);
        float2 f3 = __half22float2(*(__half2*)&v.w);
        acc[0] += f0.x; acc[1] += f0.y;
        acc[2] += f1.x; acc[3] += f1.y;
        acc[4] += f2.x; acc[5] += f2.y;
        acc[6] += f3.x; acc[7] += f3.y;
    }
    float inv = g_invdeg[w];
    __half2 h0 = __floats2half2_rn(acc[0] * inv, acc[1] * inv);
    __half2 h1 = __floats2half2_rn(acc[2] * inv, acc[3] * inv);
    __half2 h2 = __floats2half2_rn(acc[4] * inv, acc[5] * inv);
    __half2 h3 = __floats2half2_rn(acc[6] * inv, acc[7] * inv);
    uint4 o;
    o.x = *(uint32_t*)&h0; o.y = *(uint32_t*)&h1;
    o.z = *(uint32_t*)&h2; o.w = *(uint32_t*)&h3;
    *(uint4*)(outh + (size_t)w * 256 + lane * 8) = o;
}

// -------------------- f16 tensor-core GEMM (mma.sync m16n8k16) --------------------
// C = act( [A1|A2] @ Wt^T + bias ), Wt = [Ncol][Ktot] f16 (K-major per out-col).
// K counted in HALVES; K1, K2 multiples of 64. Block tile 128 x (NTILES*16) x 64(half).
// Smem: uint32 = half2; KSTR=36 keeps the 4*grp+q all-banks trick from the tf32 kernel.

#define TBM 128
#define KSTR 36

__device__ __forceinline__ void mma_f16(float c[4],
                                        uint32_t a0, uint32_t a1, uint32_t a2, uint32_t a3,
                                        uint32_t b0, uint32_t b1) {
    asm volatile(
        "mma.sync.aligned.m16n8k16.row.col.f32.f16.f16.f32 "
        "{%0,%1,%2,%3}, {%4,%5,%6,%7}, {%8,%9}, {%0,%1,%2,%3};"
        : "+f"(c[0]), "+f"(c[1]), "+f"(c[2]), "+f"(c[3])
        : "r"(a0), "r"(a1), "r"(a2), "r"(a3), "r"(b0), "r"(b1));
}

template <int NTILES, int AHALF, int OUTHALF>
__global__ __launch_bounds__(256) void gemm_f16_kernel(
    const void* __restrict__ A1v, int lda1, int K1,
    const void* __restrict__ A2v, int lda2, int K2,
    const __half* __restrict__ Wt, int ldw,
    const float* __restrict__ bias,
    void* __restrict__ Cv, int ldc,
    int M, int do_relu)
{
    constexpr int TBN = NTILES * 16;
    constexpr int B_IT = TBN / 32;       // uint4 B loads per thread per tile

    __shared__ uint32_t As[TBM][KSTR];   // [row][k/2] half2
    __shared__ uint32_t Bs[TBN][KSTR];   // [n][k/2] half2

    int tid = threadIdx.x;
    int lane = tid & 31;
    int wid = tid >> 5;
    int grp = lane >> 2;
    int q = lane & 3;
    int warp_m = (wid & 3) * 32;
    int warp_n = (wid >> 2) * (NTILES * 8);
    int rowbase = blockIdx.y * TBM;
    int colbase = blockIdx.x * TBN;

    float acc[2][NTILES][4];
#pragma unroll
    for (int mt = 0; mt < 2; mt++)
#pragma unroll
        for (int nt = 0; nt < NTILES; nt++)
#pragma unroll
            for (int r = 0; r < 4; r++) acc[mt][nt][r] = 0.f;

    int K = K1 + K2;                     // halves
    uint4 ar[4], br[B_IT];

    // ---- prologue: load k-tile 0 into regs ----
    {
        const void* Av; int lda, ko;
        if (0 < K1) { Av = A1v; lda = lda1; ko = 0; }
        else        { Av = A2v; lda = lda2; ko = 0; }
#pragma unroll
        for (int it = 0; it < 4; it++) {
            int s = tid + it * 256;
            int row = s >> 3, k8 = s & 7;
            int r = rowbase + row;
            uint4 u = make_uint4(0, 0, 0, 0);
            if (r < M) {
                if (AHALF) {
                    u = *(const uint4*)((const __half*)Av + (size_t)r * lda + ko + k8 * 8);
                } else {
                    const float* ap = (const float*)Av + (size_t)r * lda + ko + k8 * 8;
                    float4 f0 = *(const float4*)ap;
                    float4 f1 = *(const float4*)(ap + 4);
                    __half2 h0 = __floats2half2_rn(f0.x, f0.y);
                    __half2 h1 = __floats2half2_rn(f0.z, f0.w);
                    __half2 h2 = __floats2half2_rn(f1.x, f1.y);
                    __half2 h3 = __floats2half2_rn(f1.z, f1.w);
                    u.x = *(uint32_t*)&h0; u.y = *(uint32_t*)&h1;
                    u.z = *(uint32_t*)&h2; u.w = *(uint32_t*)&h3;
                }
            }
            ar[it] = u;
        }
#pragma unroll
        for (int it = 0; it < B_IT; it++) {
            int s = tid + it * 256;
            int n = s >> 3, k8 = s & 7;
            br[it] = *(const uint4*)(Wt + (size_t)(colbase + n) * ldw + k8 * 8);
        }
    }

    for (int kb = 0; kb < K; kb += 64) {
        // ---- regs -> smem ----
#pragma unroll
        for (int it = 0; it < 4; it++) {
            int s = tid + it * 256;
            int row = s >> 3, k8 = s & 7;
            *(uint4*)&As[row][k8 * 4] = ar[it];
        }
#pragma unroll
        for (int it = 0; it < B_IT; it++) {
            int s = tid + it * 256;
            int n = s >> 3, k8 = s & 7;
            *(uint4*)&Bs[n][k8 * 4] = br[it];
        }
        __syncthreads();

        // ---- prefetch next k-tile ----
        int kn = kb + 64;
        if (kn < K) {
            const void* Av; int lda, ko;
            if (kn < K1) { Av = A1v; lda = lda1; ko = kn; }
            else         { Av = A2v; lda = lda2; ko = kn - K1; }
#pragma unroll
            for (int it = 0; it < 4; it++) {
                int s = tid + it * 256;
                int row = s >> 3, k8 = s & 7;
                int r = rowbase + row;
                uint4 u = make_uint4(0, 0, 0, 0);
                if (r < M) {
                    if (AHALF) {
                        u = *(const uint4*)((const __half*)Av + (size_t)r * lda + ko + k8 * 8);
                    } else {
                        const float* ap = (const float*)Av + (size_t)r * lda + ko + k8 * 8;
                        float4 f0 = *(const float4*)ap;
                        float4 f1 = *(const float4*)(ap + 4);
                        __half2 h0 = __floats2half2_rn(f0.x, f0.y);
                        __half2 h1 = __floats2half2_rn(f0.z, f0.w);
                        __half2 h2 = __floats2half2_rn(f1.x, f1.y);
                        __half2 h3 = __floats2half2_rn(f1.z, f1.w);
                        u.x = *(uint32_t*)&h0; u.y = *(uint32_t*)&h1;
                        u.z = *(uint32_t*)&h2; u.w = *(uint32_t*)&h3;
                    }
                }
                ar[it] = u;
            }
#pragma unroll
            for (int it = 0; it < B_IT; it++) {
                int s = tid + it * 256;
                int n = s >> 3, k8 = s & 7;
                br[it] = *(const uint4*)(Wt + (size_t)(colbase + n) * ldw + kn + k8 * 8);
            }
        }

        // ---- MMA over smem tile: 4 chunks of k=16 halves (8 uint32) ----
#pragma unroll
        for (int kc = 0; kc < 32; kc += 8) {
            uint32_t a[2][4];
#pragma unroll
            for (int mt = 0; mt < 2; mt++) {
                int r = warp_m + mt * 16 + grp;
                a[mt][0] = As[r][kc + q];
                a[mt][1] = As[r + 8][kc + q];
                a[mt][2] = As[r][kc + q + 4];
                a[mt][3] = As[r + 8][kc + q + 4];
            }
#pragma unroll
            for (int nt = 0; nt < NTILES; nt++) {
                int c = warp_n + nt * 8 + grp;
                uint32_t b0 = Bs[c][kc + q];
                uint32_t b1 = Bs[c][kc + q + 4];
#pragma unroll
                for (int mt = 0; mt < 2; mt++)
                    mma_f16(acc[mt][nt], a[mt][0], a[mt][1], a[mt][2], a[mt][3], b0, b1);
            }
        }
        __syncthreads();
    }

    // ---- epilogue ----
#pragma unroll
    for (int nt = 0; nt < NTILES; nt++) {
        int ccol = colbase + warp_n + nt * 8 + q * 2;
        float bv0 = bias[ccol], bv1 = bias[ccol + 1];
#pragma unroll
        for (int mt = 0; mt < 2; mt++) {
            int r0 = rowbase + warp_m + mt * 16 + grp;
            int r1 = r0 + 8;
            float v0 = acc[mt][nt][0] + bv0;
            float v1 = acc[mt][nt][1] + bv1;
            float v2 = acc[mt][nt][2] + bv0;
            float v3 = acc[mt][nt][3] + bv1;
            if (do_relu) {
                v0 = fmaxf(v0, 0.f); v1 = fmaxf(v1, 0.f);
                v2 = fmaxf(v2, 0.f); v3 = fmaxf(v3, 0.f);
            }
            if (OUTHALF) {
                __half* C = (__half*)Cv;
                if (r0 < M) {
                    __half2 o = __floats2half2_rn(v0, v1);
                    *(__half2*)&C[(size_t)r0 * ldc + ccol] = o;
                }
                if (r1 < M) {
                    __half2 o = __floats2half2_rn(v2, v3);
                    *(__half2*)&C[(size_t)r1 * ldc + ccol] = o;
                }
            } else {
                float* C = (float*)Cv;
                if (r0 < M) { float2 o = {v0, v1}; *(float2*)&C[(size_t)r0 * ldc + ccol] = o; }
                if (r1 < M) { float2 o = {v2, v3}; *(float2*)&C[(size_t)r1 * ldc + ccol] = o; }
            }
        }
    }
}

// -------------------- launch --------------------
extern "C" void kernel_launch(void* const* d_in, const int* in_sizes, int n_in,
                              void* d_out, int out_size) {
    const float* x   = (const float*)d_in[0];
    const void*  ei  = d_in[1];
    const float* Wl0 = (const float*)d_in[2];
    const float* Wr0 = (const float*)d_in[3];
    const float* b0  = (const float*)d_in[4];
    const float* Wl1 = (const float*)d_in[5];
    const float* Wr1 = (const float*)d_in[6];
    const float* b1  = (const float*)d_in[7];
    const float* Wf  = (const float*)d_in[8];
    const float* bf  = (const float*)d_in[9];
    (void)n_in; (void)out_size;

    int Nn = in_sizes[0] / 128;   // 100000
    int Ee = in_sizes[1] / 2;     // 3200000

    float* out = (float*)d_out;                 // [N, 64]
    float* emb = out + (size_t)Nn * 64;         // [N, 256]

    void *p_agg, *p_hf, *p_aggh, *p_wt;
    cudaGetSymbolAddress(&p_agg, g_agg);
    cudaGetSymbolAddress(&p_hf, g_hf);
    cudaGetSymbolAddress(&p_aggh, g_aggh);
    cudaGetSymbolAddress(&p_wt, g_wt);
    float* agg = (float*)p_agg;
    __half* hf = (__half*)p_hf;
    __half* aggh = (__half*)p_aggh;
    __half* W0t = (__half*)p_wt;                // [256][256]
    __half* W1t = W0t + 256 * 256;              // [256][512]
    __half* Wft = W1t + 256 * 512;              // [64][256]

    int tiles = (Nn + TBM - 1) / TBM;
    dim3 gemm_grid(2, tiles);                   // TBN=128, Ncol=256
    dim3 head_grid(1, tiles);                   // TBN=64,  Ncol=64

    // 0) dtype detect
    detect_kernel<<<1, 64>>>(ei, Nn);

    // 1) CSR build (by dst)
    zero_count_kernel<<<(Nn + 256) / 256, 256>>>(Nn);
    hist_kernel<<<(Ee + 255) / 256, 256>>>(ei, Ee);
    scan_p1<<<SCAN_BLOCKS, SCAN_THREADS>>>(Nn);
    scan_p2<<<1, SCAN_BLOCKS>>>(Ee, Nn);
    scan_p3<<<SCAN_BLOCKS, SCAN_THREADS>>>(Nn);
    scatter_kernel<<<(Ee + 255) / 256, 256>>>(ei, Ee);

    // 1b) weight convert+transpose to f16 (K-major per output column)
    wconv_kernel<<<(128 * 256 + 255) / 256, 256>>>(Wl0, W0t, 0, 128, 256, 256);
    wconv_kernel<<<(128 * 256 + 255) / 256, 256>>>(Wr0, W0t, 128, 128, 256, 256);
    wconv_kernel<<<(256 * 256 + 255) / 256, 256>>>(Wl1, W1t, 0, 256, 512, 256);
    wconv_kernel<<<(256 * 256 + 255) / 256, 256>>>(Wr1, W1t, 256, 256, 512, 256);
    wconv_kernel<<<(256 * 64 + 255) / 256, 256>>>(Wf, Wft, 0, 256, 256, 64);

    // 2) layer 0: agg0 (fp32), then f16 GEMM  hf = relu([x|agg0] @ W0t^T + b0)
    agg_f32_kernel<<<(Nn + 7) / 8, 256>>>((const float4*)x, (float4*)agg, Nn);
    gemm_f16_kernel<8, 0, 1><<<gemm_grid, 256>>>(
        x, 128, 128, agg, 128, 128, W0t, 256, b0, hf, 256, Nn, 1);

    // 3) layer 1: f16 agg1, then f16 GEMM  emb = relu([hf|aggh] @ W1t^T + b1)
    agg_f16_kernel<<<(Nn + 7) / 8, 256>>>(hf, aggh, Nn);
    gemm_f16_kernel<8, 1, 0><<<gemm_grid, 256>>>(
        hf, 256, 256, aggh, 256, 256, W1t, 512, b1, emb, 256, Nn, 1);

    // 4) head: out = emb @ Wft^T + bf
    gemm_f16_kernel<4, 0, 0><<<head_grid, 256>>>(
        emb, 256, 256, nullptr, 0, 0, Wft, 256, bf, out, 64, Nn, 0);
}